// round 4
// baseline (speedup 1.0000x reference)
#include <cuda_runtime.h>
#include <cstdint>
#include <math.h>

// Problem dims
#define BATCH 8
#define S1V   2048
#define S2V   2048
#define HV    1024

// ----------------------------------------------------------------------------
// Scratch (device globals — no allocation allowed in kernel_launch)
// ----------------------------------------------------------------------------
__device__ float g_qproj[(size_t)BATCH * S1V * HV];    // 64 MB  [B,S1,H]
__device__ float g_scores[(size_t)BATCH * S2V * S1V];  // 128 MB [B,S2,S1] (transposed logits)
__device__ int   g_maskT[(size_t)BATCH * S2V * S1V];   // 128 MB [B,S2,S1] (int32 mask)

// ----------------------------------------------------------------------------
// Tiled fp32 GEMM: C[M,N] = A[M,K] * op(B) (+ bias)
//   TRANS_B=true : B is [N,K] row-major (NT gemm)
//   TRANS_B=false: B is [K,N] row-major (NN gemm)
// Block tile 128x64, K-tile 16, 256 threads, 8x4 per-thread micro-tile.
// M % 128 == 0, N % 64 == 0, K % 16 == 0 (all true for this problem).
// ----------------------------------------------------------------------------
template <bool TRANS_B, bool HAS_BIAS>
__global__ __launch_bounds__(256) void gemm_kernel(
    const float* __restrict__ A, const float* __restrict__ B,
    const float* __restrict__ bias, float* __restrict__ C,
    int M, int N, int K,
    long long strideA, long long strideB, long long strideC)
{
    const int BM = 128, BN = 64, BK = 16;
    __shared__ float As[BM][BK + 1];   // [128][17]
    __shared__ float Bs[BK][BN + 4];   // [16][68]

    const int bz = blockIdx.z;
    A += (long long)bz * strideA;
    B += (long long)bz * strideB;
    C += (long long)bz * strideC;

    const int m0 = blockIdx.y * BM;
    const int n0 = blockIdx.x * BN;
    const int t  = threadIdx.x;
    const int tx = t & 15;    // 0..15 -> 4 cols each
    const int ty = t >> 4;    // 0..15 -> 8 rows each

    float acc[8][4];
#pragma unroll
    for (int i = 0; i < 8; i++)
#pragma unroll
        for (int j = 0; j < 4; j++) acc[i][j] = 0.f;

    for (int k0 = 0; k0 < K; k0 += BK) {
        // ---- load A tile: 128x16 floats, two float4 per thread ----
#pragma unroll
        for (int p = 0; p < 2; p++) {
            int lin = t * 4 + p * 1024;
            int r = lin >> 4, c = lin & 15;
            float4 v = *(const float4*)(A + (long long)(m0 + r) * K + k0 + c);
            As[r][c]     = v.x;
            As[r][c + 1] = v.y;
            As[r][c + 2] = v.z;
            As[r][c + 3] = v.w;
        }
        // ---- load B tile ----
        if (TRANS_B) {
            // B[n][k]: 64x16 floats, one float4 per thread; store transposed Bs[k][n]
            int lin = t * 4;
            int r = lin >> 4, c = lin & 15;    // r: n-idx, c: k-idx
            float4 v = *(const float4*)(B + (long long)(n0 + r) * K + k0 + c);
            Bs[c][r]     = v.x;
            Bs[c + 1][r] = v.y;
            Bs[c + 2][r] = v.z;
            Bs[c + 3][r] = v.w;
        } else {
            // B[k][n]: 16x64 floats, one float4 per thread, direct store
            int lin = t * 4;
            int r = lin >> 6, c = lin & 63;    // r: k-idx, c: n-idx
            float4 v = *(const float4*)(B + (long long)(k0 + r) * N + n0 + c);
            *(float4*)&Bs[r][c] = v;
        }
        __syncthreads();

#pragma unroll
        for (int kk = 0; kk < BK; kk++) {
            float a[8];
#pragma unroll
            for (int i = 0; i < 8; i++) a[i] = As[ty * 8 + i][kk];
            float4 bv = *(const float4*)&Bs[kk][tx * 4];
            float bj[4] = {bv.x, bv.y, bv.z, bv.w};
#pragma unroll
            for (int i = 0; i < 8; i++)
#pragma unroll
                for (int j = 0; j < 4; j++) acc[i][j] = fmaf(a[i], bj[j], acc[i][j]);
        }
        __syncthreads();
    }

    // ---- epilogue ----
    float bx = 0.f, by = 0.f, bzv = 0.f, bw = 0.f;
    if (HAS_BIAS) {
        int n = n0 + tx * 4;
        bx = bias[n]; by = bias[n + 1]; bzv = bias[n + 2]; bw = bias[n + 3];
    }
#pragma unroll
    for (int i = 0; i < 8; i++) {
        int m = m0 + ty * 8 + i;
        float4 o;
        o.x = acc[i][0] + bx;
        o.y = acc[i][1] + by;
        o.z = acc[i][2] + bzv;
        o.w = acc[i][3] + bw;
        *(float4*)(C + (long long)m * N + n0 + tx * 4) = o;
    }
}

// ----------------------------------------------------------------------------
// int32 transpose of mask: mask[B][S1][S2] -> maskT[B][S2][S1]
// (harness delivers bool inputs as int32)
// ----------------------------------------------------------------------------
__global__ void mask_transpose_kernel(const int* __restrict__ mask,
                                      int* __restrict__ maskT)
{
    __shared__ int tile[32][33];
    int b  = blockIdx.z;
    int q0 = blockIdx.y * 32;   // S1 dim
    int k0 = blockIdx.x * 32;   // S2 dim
    const int* mb  = mask  + (size_t)b * S1V * S2V;
    int*       mtb = maskT + (size_t)b * S2V * S1V;
    int tx = threadIdx.x, ty = threadIdx.y;   // 32 x 8
#pragma unroll
    for (int i = 0; i < 32; i += 8)
        tile[ty + i][tx] = mb[(size_t)(q0 + ty + i) * S2V + k0 + tx];
    __syncthreads();
#pragma unroll
    for (int i = 0; i < 32; i += 8)
        mtb[(size_t)(k0 + ty + i) * S1V + q0 + tx] = tile[tx][ty + i];
}

// ----------------------------------------------------------------------------
// Fused masked softmax over S1 (row length 2048), one block per (b,k) row.
// mask!=0 -> -inf (weight 0). Writes weights directly to output region.
// ----------------------------------------------------------------------------
__device__ __forceinline__ float warpReduceMax(float v) {
#pragma unroll
    for (int o = 16; o > 0; o >>= 1) v = fmaxf(v, __shfl_xor_sync(0xffffffffu, v, o));
    return v;
}
__device__ __forceinline__ float warpReduceSum(float v) {
#pragma unroll
    for (int o = 16; o > 0; o >>= 1) v += __shfl_xor_sync(0xffffffffu, v, o);
    return v;
}

__global__ __launch_bounds__(256) void softmax_kernel(
    const float* __restrict__ scores, const int* __restrict__ maskT,
    float* __restrict__ weights)
{
    __shared__ float smax[8];
    __shared__ float ssum[8];
    __shared__ float sbcast[2];

    const long long row = blockIdx.x;   // 0 .. B*S2-1
    const float* s = scores  + row * S1V;
    const int*   m = maskT   + row * S1V;
    float*       w = weights + row * S1V;
    const int t    = threadIdx.x;       // 256 threads, 8 elems each
    const int lane = t & 31, wid = t >> 5;

    float vals[8];
    float mx = -INFINITY;
#pragma unroll
    for (int i = 0; i < 8; i++) {
        int idx = t + i * 256;
        float v = m[idx] ? -INFINITY : s[idx];
        vals[i] = v;
        mx = fmaxf(mx, v);
    }
    mx = warpReduceMax(mx);
    if (lane == 0) smax[wid] = mx;
    __syncthreads();
    if (wid == 0) {
        float x = (lane < 8) ? smax[lane] : -INFINITY;
        x = warpReduceMax(x);
        if (lane == 0) sbcast[0] = x;
    }
    __syncthreads();
    mx = sbcast[0];

    float sum = 0.f;
#pragma unroll
    for (int i = 0; i < 8; i++) {
        vals[i] = __expf(vals[i] - mx);
        sum += vals[i];
    }
    sum = warpReduceSum(sum);
    if (lane == 0) ssum[wid] = sum;
    __syncthreads();
    if (wid == 0) {
        float x = (lane < 8) ? ssum[lane] : 0.f;
        x = warpReduceSum(x);
        if (lane == 0) sbcast[1] = x;
    }
    __syncthreads();
    float inv = 1.f / sbcast[1];
#pragma unroll
    for (int i = 0; i < 8; i++) w[t + i * 256] = vals[i] * inv;
}

// ----------------------------------------------------------------------------
// kernel_launch
// Inputs (setup_inputs order): value, key, query, mask(bool->int32), W, b
// Output: context [B,S2,H] followed by weights [B,S2,S1], fp32
// ----------------------------------------------------------------------------
extern "C" void kernel_launch(void* const* d_in, const int* in_sizes, int n_in,
                              void* d_out, int out_size)
{
    const float* value = (const float*)d_in[0];
    const float* key   = (const float*)d_in[1];
    const float* query = (const float*)d_in[2];
    const int*   mask  = (const int*)d_in[3];
    const float* W     = (const float*)d_in[4];
    const float* bias  = (const float*)d_in[5];

    float* ctx     = (float*)d_out;                                  // [B,S2,H]
    float* weights = (float*)d_out + (size_t)BATCH * S2V * HV;       // [B,S2,S1]

    float* qproj;  float* scores;  int* maskT;
    cudaGetSymbolAddress((void**)&qproj,  g_qproj);
    cudaGetSymbolAddress((void**)&scores, g_scores);
    cudaGetSymbolAddress((void**)&maskT,  g_maskT);

    // 1) q_proj = query @ W^T + b   (M=16384, N=1024, K=1024, NT)
    {
        dim3 grid(HV / 64, (BATCH * S1V) / 128, 1);
        gemm_kernel<true, true><<<grid, 256>>>(
            query, W, bias, qproj,
            BATCH * S1V, HV, HV, 0, 0, 0);
    }

    // 2) mask transpose [B,S1,S2] -> [B,S2,S1]
    {
        dim3 grid(S2V / 32, S1V / 32, BATCH);
        mask_transpose_kernel<<<grid, dim3(32, 8)>>>(mask, maskT);
    }

    // 3) scoresT[b] = key[b] @ q_proj[b]^T   (per-batch M=S2, N=S1, K=H, NT)
    {
        dim3 grid(S1V / 64, S2V / 128, BATCH);
        gemm_kernel<true, false><<<grid, 256>>>(
            key, qproj, nullptr, scores,
            S2V, S1V, HV,
            (long long)S2V * HV, (long long)S1V * HV, (long long)S2V * S1V);
    }

    // 4) masked softmax over S1 -> weights (written straight into output)
    softmax_kernel<<<BATCH * S2V, 256>>>(scores, maskT, weights);

    // 5) context[b] = weights[b] @ value[b]  (per-batch M=S2, N=H, K=S1, NN)
    {
        dim3 grid(HV / 64, S2V / 128, BATCH);
        gemm_kernel<false, false><<<grid, 256>>>(
            weights, value, nullptr, ctx,
            S2V, HV, S1V,
            (long long)S2V * S1V, (long long)S1V * HV, (long long)S2V * HV);
    }
}

// round 8
// speedup vs baseline: 2.9954x; 2.9954x over previous
#include <cuda_runtime.h>
#include <cuda_bf16.h>
#include <cstdint>
#include <math.h>

#define BATCH 8
#define S1V   2048
#define S2V   2048
#define HV    1024

typedef __nv_bfloat16 bf16;

// ----------------------------------------------------------------------------
// Scratch (device globals)
// ----------------------------------------------------------------------------
__device__ bf16 g_qh [(size_t)BATCH * S1V * HV];
__device__ bf16 g_ql [(size_t)BATCH * S1V * HV];
__device__ bf16 g_kh [(size_t)BATCH * S2V * HV];
__device__ bf16 g_kl [(size_t)BATCH * S2V * HV];
__device__ bf16 g_wh [(size_t)HV * HV];
__device__ bf16 g_wl [(size_t)HV * HV];
__device__ bf16 g_qph[(size_t)BATCH * S1V * HV];
__device__ bf16 g_qpl[(size_t)BATCH * S1V * HV];
__device__ bf16 g_vth[(size_t)BATCH * HV * S1V];   // valueT [B,H,S1]
__device__ bf16 g_vtl[(size_t)BATCH * HV * S1V];
__device__ bf16 g_wgh[(size_t)BATCH * S2V * S1V];
__device__ bf16 g_wgl[(size_t)BATCH * S2V * S1V];
__device__ float         g_scores[(size_t)BATCH * S2V * S1V];
__device__ unsigned char g_maskT [(size_t)BATCH * S2V * S1V];

// ----------------------------------------------------------------------------
// PTX helpers (all plain sm_80+ features — NO tcgen05/'a'-suffix instructions)
// ----------------------------------------------------------------------------
__device__ __forceinline__ uint32_t smem_u32(const void* p) {
    uint32_t a;
    asm("{ .reg .u64 t; cvta.to.shared.u64 t, %1; cvt.u32.u64 %0, t; }" : "=r"(a) : "l"(p));
    return a;
}
__device__ __forceinline__ void cp_async16(uint32_t dst, const void* src) {
    asm volatile("cp.async.cg.shared.global [%0], [%1], 16;" :: "r"(dst), "l"(src));
}
#define CP_COMMIT() asm volatile("cp.async.commit_group;" ::: "memory")
#define CP_WAIT0()  asm volatile("cp.async.wait_group 0;" ::: "memory")
#define CP_WAIT1()  asm volatile("cp.async.wait_group 1;" ::: "memory")

__device__ __forceinline__ void ldsm4(uint32_t r[4], uint32_t addr) {
    asm volatile("ldmatrix.sync.aligned.m8n8.x4.shared.b16 {%0,%1,%2,%3}, [%4];"
                 : "=r"(r[0]), "=r"(r[1]), "=r"(r[2]), "=r"(r[3]) : "r"(addr));
}
__device__ __forceinline__ void mma16816(float c[4], const uint32_t a[4],
                                         const uint32_t b0, const uint32_t b1) {
    asm volatile("mma.sync.aligned.m16n8k16.row.col.f32.bf16.bf16.f32 "
                 "{%0,%1,%2,%3}, {%4,%5,%6,%7}, {%8,%9}, {%0,%1,%2,%3};"
                 : "+f"(c[0]), "+f"(c[1]), "+f"(c[2]), "+f"(c[3])
                 : "r"(a[0]), "r"(a[1]), "r"(a[2]), "r"(a[3]), "r"(b0), "r"(b1));
}

#define SWZ(o) ((o) ^ (((o) >> 3) & 0x70))

// ----------------------------------------------------------------------------
// Split-bf16 NT GEMM on mma.sync:  C[M,N] = (Ah+Al)[M,K] @ (Bh+Bl)[N,K]^T
// Block tile 128x128, K-chunk 64 (bf16), SW128 smem, 2-stage cp.async pipeline.
// 8 warps in 2(M) x 4(N); warp tile 64x32; mma.m16n8k16, 3 split passes.
// EPI: 0 = fp32 store to Cf; 1 = +bias, hi/lo bf16 split to Ch/Cl.
// ----------------------------------------------------------------------------
#define TILE_M 128
#define TILE_N 128
#define TILE_K 64
#define STAGE_BYTES 65536   // Ah 16K | Al 16K | Bh 16K | Bl 16K
#define SMEM_BYTES  (2 * STAGE_BYTES)

__device__ __forceinline__ void load_stage(
    uint32_t sbase,
    const bf16* Ah, const bf16* Al, const bf16* Bh, const bf16* Bl,
    long long m0, long long n0, long long ldA, long long ldB, int k0, int tid)
{
#pragma unroll
    for (int i = tid; i < 1024; i += 256) {            // A: 128 rows x 128B
        int r = i >> 3, c = i & 7;
        uint32_t sw = SWZ(r * 128 + c * 16);
        long long goff = (m0 + r) * ldA + k0 + c * 8;
        cp_async16(sbase + sw,         Ah + goff);
        cp_async16(sbase + 16384 + sw, Al + goff);
    }
#pragma unroll
    for (int i = tid; i < 1024; i += 256) {            // B: 128 rows x 128B
        int r = i >> 3, c = i & 7;
        uint32_t sw = SWZ(r * 128 + c * 16);
        long long goff = (n0 + r) * ldB + k0 + c * 8;
        cp_async16(sbase + 32768 + sw, Bh + goff);
        cp_async16(sbase + 49152 + sw, Bl + goff);
    }
}

template <int EPI>
__global__ __launch_bounds__(256) void mma_gemm(
    const bf16* __restrict__ Ah, const bf16* __restrict__ Al,
    const bf16* __restrict__ Bh, const bf16* __restrict__ Bl,
    const float* __restrict__ bias,
    float* __restrict__ Cf, bf16* __restrict__ Ch, bf16* __restrict__ Cl,
    int K, int N,
    long long ldA, long long ldB,
    long long sA, long long sB, long long sC)
{
    extern __shared__ char smem[];
    const uint32_t sb = smem_u32(smem);

    const int tid  = threadIdx.x;
    const int wid  = tid >> 5;
    const int lane = tid & 31;
    const int wm = wid & 1;      // 2 M-groups of 64
    const int wn = wid >> 1;     // 4 N-groups of 32

    const long long bz = blockIdx.z;
    Ah += bz * sA;  Al += bz * sA;
    Bh += bz * sB;  Bl += bz * sB;
    const long long m0 = (long long)blockIdx.y * TILE_M;
    const long long n0 = (long long)blockIdx.x * TILE_N;

    // ldmatrix lane addressing (tile index g = lane>>3):
    //   A: m-block = g&1, k-half = g>>1
    //   B: n-block = g>>1, k-half = g&1
    const int g  = lane >> 3;
    const int lr = lane & 7;
    const int rowA = wm * 64 + (g & 1) * 8 + lr;
    const int kbA  = (g >> 1) * 16;
    const int rowB = wn * 32 + (g >> 1) * 8 + lr;
    const int kbB  = (g & 1) * 16;

    float acc[4][4][4];
#pragma unroll
    for (int i = 0; i < 4; i++)
#pragma unroll
        for (int j = 0; j < 4; j++)
#pragma unroll
            for (int r = 0; r < 4; r++) acc[i][j][r] = 0.f;

    const int NKC = K / TILE_K;

    load_stage(sb, Ah, Al, Bh, Bl, m0, n0, ldA, ldB, 0, tid);
    CP_COMMIT();

    for (int kc = 0; kc < NKC; ++kc) {
        const uint32_t sbase = sb + (kc & 1) * STAGE_BYTES;
        if (kc + 1 < NKC) {
            load_stage(sb + ((kc + 1) & 1) * STAGE_BYTES,
                       Ah, Al, Bh, Bl, m0, n0, ldA, ldB, (kc + 1) * TILE_K, tid);
            CP_COMMIT();
            CP_WAIT1();
        } else {
            CP_WAIT0();
        }
        __syncthreads();

#pragma unroll
        for (int ks = 0; ks < 4; ++ks) {
            uint32_t ah[4][4], al[4][4];
#pragma unroll
            for (int i = 0; i < 4; i++) {
                uint32_t off = SWZ((uint32_t)((rowA + i * 16) * 128 + ks * 32 + kbA));
                ldsm4(ah[i], sbase + off);
                ldsm4(al[i], sbase + 16384 + off);
            }
            uint32_t bh[2][4], bl[2][4];
#pragma unroll
            for (int jj = 0; jj < 2; jj++) {
                uint32_t off = SWZ((uint32_t)((rowB + jj * 16) * 128 + ks * 32 + kbB));
                ldsm4(bh[jj], sbase + 32768 + off);
                ldsm4(bl[jj], sbase + 49152 + off);
            }
#pragma unroll
            for (int i = 0; i < 4; i++)
#pragma unroll
                for (int jj = 0; jj < 2; jj++)
#pragma unroll
                    for (int nb = 0; nb < 2; nb++) {
                        float* c = acc[i][jj * 2 + nb];
                        mma16816(c, ah[i], bh[jj][nb * 2], bh[jj][nb * 2 + 1]); // hi*hi
                        mma16816(c, ah[i], bl[jj][nb * 2], bl[jj][nb * 2 + 1]); // hi*lo
                        mma16816(c, al[i], bh[jj][nb * 2], bh[jj][nb * 2 + 1]); // lo*hi
                    }
        }
        __syncthreads();
    }

    // ---- epilogue ----
    const int qr = lane >> 2;          // row within m16
    const int qc = (lane & 3) * 2;     // col within n8
#pragma unroll
    for (int i = 0; i < 4; i++) {
        long long mr0 = m0 + wm * 64 + i * 16 + qr;
#pragma unroll
        for (int j = 0; j < 4; j++) {
            long long n = n0 + wn * 32 + j * 8 + qc;
            float* c = acc[i][j];
            if (EPI == 0) {
                float2* p0 = (float2*)(Cf + bz * sC + mr0 * (long long)N + n);
                float2* p1 = (float2*)(Cf + bz * sC + (mr0 + 8) * (long long)N + n);
                *p0 = make_float2(c[0], c[1]);
                *p1 = make_float2(c[2], c[3]);
            } else {
                float b0 = bias[n], b1 = bias[n + 1];
#pragma unroll
                for (int h = 0; h < 2; h++) {
                    float x0 = c[2 * h]     + b0;
                    float x1 = c[2 * h + 1] + b1;
                    bf16 h0 = __float2bfloat16(x0);
                    bf16 h1 = __float2bfloat16(x1);
                    bf16 l0 = __float2bfloat16(x0 - __bfloat162float(h0));
                    bf16 l1 = __float2bfloat16(x1 - __bfloat162float(h1));
                    long long off = (mr0 + 8 * h) * (long long)N + n;
                    *(uint32_t*)(Ch + off) =
                        (uint32_t)__bfloat16_as_ushort(h0) | ((uint32_t)__bfloat16_as_ushort(h1) << 16);
                    *(uint32_t*)(Cl + off) =
                        (uint32_t)__bfloat16_as_ushort(l0) | ((uint32_t)__bfloat16_as_ushort(l1) << 16);
                }
            }
        }
    }
}

// ----------------------------------------------------------------------------
// fp32 -> hi/lo bf16 elementwise split
// ----------------------------------------------------------------------------
__global__ __launch_bounds__(256) void split_kernel(
    const float4* __restrict__ in, uint32_t* __restrict__ hi, uint32_t* __restrict__ lo)
{
    long long i = (long long)blockIdx.x * 256 + threadIdx.x;
    float4 v = in[i];
    bf16 h0 = __float2bfloat16(v.x), h1 = __float2bfloat16(v.y);
    bf16 h2 = __float2bfloat16(v.z), h3 = __float2bfloat16(v.w);
    bf16 l0 = __float2bfloat16(v.x - __bfloat162float(h0));
    bf16 l1 = __float2bfloat16(v.y - __bfloat162float(h1));
    bf16 l2 = __float2bfloat16(v.z - __bfloat162float(h2));
    bf16 l3 = __float2bfloat16(v.w - __bfloat162float(h3));
    hi[2 * i]     = (uint32_t)__bfloat16_as_ushort(h0) | ((uint32_t)__bfloat16_as_ushort(h1) << 16);
    hi[2 * i + 1] = (uint32_t)__bfloat16_as_ushort(h2) | ((uint32_t)__bfloat16_as_ushort(h3) << 16);
    lo[2 * i]     = (uint32_t)__bfloat16_as_ushort(l0) | ((uint32_t)__bfloat16_as_ushort(l1) << 16);
    lo[2 * i + 1] = (uint32_t)__bfloat16_as_ushort(l2) | ((uint32_t)__bfloat16_as_ushort(l3) << 16);
}

// ----------------------------------------------------------------------------
// value [B,S1,H] fp32 -> valueT hi/lo [B,H,S1] bf16
// ----------------------------------------------------------------------------
__global__ void transpose_split_value(const float* __restrict__ v,
                                      bf16* __restrict__ th, bf16* __restrict__ tl)
{
    __shared__ float tile[32][33];
    int b = blockIdx.z;
    int h0 = blockIdx.x * 32, s0 = blockIdx.y * 32;
    const float* vb = v + (size_t)b * S1V * HV;
    int tx = threadIdx.x, ty = threadIdx.y;
#pragma unroll
    for (int i = 0; i < 32; i += 8)
        tile[ty + i][tx] = vb[(size_t)(s0 + ty + i) * HV + h0 + tx];
    __syncthreads();
    size_t base = (size_t)b * HV * S1V;
#pragma unroll
    for (int i = 0; i < 32; i += 8) {
        float x = tile[tx][ty + i];
        bf16 h = __float2bfloat16(x);
        bf16 l = __float2bfloat16(x - __bfloat162float(h));
        size_t o = base + (size_t)(h0 + ty + i) * S1V + s0 + tx;
        th[o] = h;
        tl[o] = l;
    }
}

// ----------------------------------------------------------------------------
// mask int32 [B,S1,S2] -> uchar maskT [B,S2,S1]
// ----------------------------------------------------------------------------
__global__ void mask_transpose_kernel(const int* __restrict__ mask,
                                      unsigned char* __restrict__ maskT)
{
    __shared__ unsigned char tile[32][33];
    int b  = blockIdx.z;
    int q0 = blockIdx.y * 32;
    int k0 = blockIdx.x * 32;
    const int*     mb  = mask  + (size_t)b * S1V * S2V;
    unsigned char* mtb = maskT + (size_t)b * S2V * S1V;
    int tx = threadIdx.x, ty = threadIdx.y;
#pragma unroll
    for (int i = 0; i < 32; i += 8)
        tile[ty + i][tx] = (unsigned char)mb[(size_t)(q0 + ty + i) * S2V + k0 + tx];
    __syncthreads();
#pragma unroll
    for (int i = 0; i < 32; i += 8)
        mtb[(size_t)(k0 + ty + i) * S1V + q0 + tx] = tile[tx][ty + i];
}

// ----------------------------------------------------------------------------
// masked softmax over S1; writes fp32 weights (output) + hi/lo bf16 (scratch)
// ----------------------------------------------------------------------------
__device__ __forceinline__ float warpMax(float v) {
#pragma unroll
    for (int o = 16; o > 0; o >>= 1) v = fmaxf(v, __shfl_xor_sync(0xffffffffu, v, o));
    return v;
}
__device__ __forceinline__ float warpSum(float v) {
#pragma unroll
    for (int o = 16; o > 0; o >>= 1) v += __shfl_xor_sync(0xffffffffu, v, o);
    return v;
}

__global__ __launch_bounds__(256) void softmax_kernel(
    const float* __restrict__ scores, const unsigned char* __restrict__ maskT,
    float* __restrict__ weights, bf16* __restrict__ wh, bf16* __restrict__ wl)
{
    __shared__ float sred[8];
    __shared__ float sbc[2];

    const long long row = blockIdx.x;
    const float*         s = scores + row * S1V;
    const unsigned char* m = maskT  + row * S1V;
    const int t = threadIdx.x, lane = t & 31, wid = t >> 5;

    float vals[8];
    float mx = -INFINITY;
#pragma unroll
    for (int i = 0; i < 8; i++) {
        int idx = t + i * 256;
        float v = m[idx] ? -INFINITY : s[idx];
        vals[i] = v;
        mx = fmaxf(mx, v);
    }
    mx = warpMax(mx);
    if (lane == 0) sred[wid] = mx;
    __syncthreads();
    if (wid == 0) {
        float x = (lane < 8) ? sred[lane] : -INFINITY;
        x = warpMax(x);
        if (lane == 0) sbc[0] = x;
    }
    __syncthreads();
    mx = sbc[0];

    float sum = 0.f;
#pragma unroll
    for (int i = 0; i < 8; i++) { vals[i] = __expf(vals[i] - mx); sum += vals[i]; }
    sum = warpSum(sum);
    if (lane == 0) sred[wid] = sum;
    __syncthreads();
    if (wid == 0) {
        float x = (lane < 8) ? sred[lane] : 0.f;
        x = warpSum(x);
        if (lane == 0) sbc[1] = x;
    }
    __syncthreads();
    float inv = 1.f / sbc[1];
#pragma unroll
    for (int i = 0; i < 8; i++) {
        long long idx = row * S1V + t + i * 256;
        float w = vals[i] * inv;
        weights[idx] = w;
        bf16 h = __float2bfloat16(w);
        wh[idx] = h;
        wl[idx] = __float2bfloat16(w - __bfloat162float(h));
    }
}

// ----------------------------------------------------------------------------
// kernel_launch
// Inputs: value, key, query, mask(int32), W, b.  Output: context | weights.
// ----------------------------------------------------------------------------
extern "C" void kernel_launch(void* const* d_in, const int* in_sizes, int n_in,
                              void* d_out, int out_size)
{
    const float* value = (const float*)d_in[0];
    const float* key   = (const float*)d_in[1];
    const float* query = (const float*)d_in[2];
    const int*   mask  = (const int*)d_in[3];
    const float* W     = (const float*)d_in[4];
    const float* bias  = (const float*)d_in[5];

    float* ctx     = (float*)d_out;                              // [B,S2,H]
    float* weights = (float*)d_out + (size_t)BATCH * S2V * HV;   // [B,S2,S1]

    bf16 *qh, *ql, *kh, *kl, *wh, *wl, *qph, *qpl, *vth, *vtl, *wgh, *wgl;
    float* scores;  unsigned char* maskT;
    cudaGetSymbolAddress((void**)&qh,  g_qh);   cudaGetSymbolAddress((void**)&ql,  g_ql);
    cudaGetSymbolAddress((void**)&kh,  g_kh);   cudaGetSymbolAddress((void**)&kl,  g_kl);
    cudaGetSymbolAddress((void**)&wh,  g_wh);   cudaGetSymbolAddress((void**)&wl,  g_wl);
    cudaGetSymbolAddress((void**)&qph, g_qph);  cudaGetSymbolAddress((void**)&qpl, g_qpl);
    cudaGetSymbolAddress((void**)&vth, g_vth);  cudaGetSymbolAddress((void**)&vtl, g_vtl);
    cudaGetSymbolAddress((void**)&wgh, g_wgh);  cudaGetSymbolAddress((void**)&wgl, g_wgl);
    cudaGetSymbolAddress((void**)&scores, g_scores);
    cudaGetSymbolAddress((void**)&maskT,  g_maskT);

    cudaFuncSetAttribute(mma_gemm<0>, cudaFuncAttributeMaxDynamicSharedMemorySize, SMEM_BYTES);
    cudaFuncSetAttribute(mma_gemm<1>, cudaFuncAttributeMaxDynamicSharedMemorySize, SMEM_BYTES);

    // 1) splits / transposes
    split_kernel<<<(BATCH * S1V * HV) / 1024, 256>>>((const float4*)query, (uint32_t*)qh, (uint32_t*)ql);
    split_kernel<<<(BATCH * S2V * HV) / 1024, 256>>>((const float4*)key,   (uint32_t*)kh, (uint32_t*)kl);
    split_kernel<<<(HV * HV) / 1024, 256>>>((const float4*)W, (uint32_t*)wh, (uint32_t*)wl);
    transpose_split_value<<<dim3(HV / 32, S1V / 32, BATCH), dim3(32, 8)>>>(value, vth, vtl);
    mask_transpose_kernel<<<dim3(S2V / 32, S1V / 32, BATCH), dim3(32, 8)>>>(mask, maskT);

    // 2) q_proj = query @ W^T + b  -> qproj hi/lo   (M=16384, N=1024, K=1024)
    mma_gemm<1><<<dim3(HV / TILE_N, (BATCH * S1V) / TILE_M, 1), 256, SMEM_BYTES>>>(
        qh, ql, wh, wl, bias,
        nullptr, qph, qpl,
        HV, HV, HV, HV, 0, 0, 0);

    // 3) scoresT[b] = key[b] @ qproj[b]^T   (M=S2, N=S1, K=H)
    mma_gemm<0><<<dim3(S1V / TILE_N, S2V / TILE_M, BATCH), 256, SMEM_BYTES>>>(
        kh, kl, qph, qpl, nullptr,
        scores, nullptr, nullptr,
        HV, S1V, HV, HV,
        (long long)S2V * HV, (long long)S1V * HV, (long long)S2V * S1V);

    // 4) masked softmax over S1
    softmax_kernel<<<BATCH * S2V, 256>>>(scores, maskT, weights, wgh, wgl);

    // 5) context[b] = weights[b] @ valueT[b]^T   (M=S2, N=H, K=S1)
    mma_gemm<0><<<dim3(HV / TILE_N, S2V / TILE_M, BATCH), 256, SMEM_BYTES>>>(
        wgh, wgl, vth, vtl, nullptr,
        ctx, nullptr, nullptr,
        S1V, HV, S1V, S1V,
        (long long)S2V * S1V, (long long)HV * S1V, (long long)S2V * HV);
}